// round 4
// baseline (speedup 1.0000x reference)
#include <cuda_runtime.h>
#include <math.h>

#define HID 64
#define MAXN 100000
#define MAXE 1600000

// Scratch (allocation-free rule: __device__ globals). 16B-aligned for vector access.
__device__ __align__(16) int   g_cnt[MAXN];
__device__ __align__(16) int   g_cur[MAXN];
__device__ __align__(16) int   g_off[MAXN + 1];
__device__ __align__(16) int   g_esrc[MAXE];
__device__ __align__(16) float g_dinv[MAXN];
__device__ __align__(16) float g_hs[(size_t)MAXN * HID];

// ---------------------------------------------------------------- init
__global__ void k_init(int N) {
    int i = blockIdx.x * blockDim.x + threadIdx.x;
    if (i < N) { g_cnt[i] = 0; g_cur[i] = 0; }
}

// ------------------------------------------------------ degree histogram
__global__ void k_count(const int* __restrict__ dst, int E, int N) {
    int i = blockIdx.x * blockDim.x + threadIdx.x;
    if (i < E) {
        unsigned d = (unsigned)dst[i];
        if (d < (unsigned)N) atomicAdd(&g_cnt[d], 1);
    }
}

// ------------------------------------------------------------- dinv
__global__ void k_dinv(int N) {
    int i = blockIdx.x * blockDim.x + threadIdx.x;
    if (i < N) g_dinv[i] = rsqrtf((float)(g_cnt[i] + 1));  // +1 self loop
}

// -------------------------------------------- exclusive scan (1 block)
__global__ void k_scan(int N) {
    __shared__ int part[1024];
    int t = threadIdx.x;
    int chunk = (N + 1023) >> 10;
    int s0 = t * chunk;
    int s1 = min(s0 + chunk, N);
    int s = 0;
    for (int i = s0; i < s1; i++) s += g_cnt[i];
    part[t] = s;
    __syncthreads();
    if (t == 0) {
        int acc = 0;
        for (int i = 0; i < 1024; i++) { int v = part[i]; part[i] = acc; acc += v; }
        g_off[N] = acc;
    }
    __syncthreads();
    int run = part[t];
    for (int i = s0; i < s1; i++) { g_off[i] = run; run += g_cnt[i]; }
}

// --------------------------------------------------- CSR edge scatter
__global__ void k_scatter(const int* __restrict__ ei, int E, int N) {
    int i = blockIdx.x * blockDim.x + threadIdx.x;
    if (i < E) {
        unsigned s = (unsigned)ei[i];
        unsigned d = (unsigned)ei[E + i];
        if (s < (unsigned)N && d < (unsigned)N) {
            int p = g_off[d] + atomicAdd(&g_cur[d], 1);
            g_esrc[p] = (int)s;
        }
    }
}

// ------------------------------------------ GEMM: hs = (x @ W) * dinv
// block = 256 threads, 32 rows/block, 8 cols/thread, K chunked by 64.
// static smem: W chunk [64x64] (16KB) + x chunk [32x65] (8.1KB) = 24.3KB
__global__ void k_gemm(const float* __restrict__ x, const float* __restrict__ W, int N) {
    __shared__ float Ws[64 * 64];
    __shared__ float xs[32 * 65];
    int tid = threadIdx.x;
    int row0 = blockIdx.x * 32;
    int c0 = (tid & 7) * 8;
    int r  = tid >> 3;

    const float4* W4 = (const float4*)W;   // harness buffer: 256B aligned
    const float4* x4 = (const float4*)x;
    float4* Ws4 = (float4*)Ws;

    float acc[8] = {0.f, 0.f, 0.f, 0.f, 0.f, 0.f, 0.f, 0.f};

    for (int kc = 0; kc < 4; kc++) {
        // W chunk: rows [kc*64, kc*64+64) of [256,64] -> 4096 contiguous floats
#pragma unroll
        for (int i = tid; i < 1024; i += 256) Ws4[i] = W4[kc * 1024 + i];
        // x chunk: 32 rows x 64 floats (16 float4 per row)
#pragma unroll
        for (int i = tid; i < 512; i += 256) {
            int rr = i >> 4, cc = i & 15;
            float4 v = (row0 + rr < N) ? x4[(size_t)(row0 + rr) * 64 + kc * 16 + cc]
                                       : make_float4(0.f, 0.f, 0.f, 0.f);
            float* d = &xs[rr * 65 + cc * 4];
            d[0] = v.x; d[1] = v.y; d[2] = v.z; d[3] = v.w;
        }
        __syncthreads();

#pragma unroll 8
        for (int k = 0; k < 64; k++) {
            float xv = xs[r * 65 + k];
            float4 wa = *(const float4*)&Ws[k * 64 + c0];
            float4 wb = *(const float4*)&Ws[k * 64 + c0 + 4];
            acc[0] += xv * wa.x; acc[1] += xv * wa.y;
            acc[2] += xv * wa.z; acc[3] += xv * wa.w;
            acc[4] += xv * wb.x; acc[5] += xv * wb.y;
            acc[6] += xv * wb.z; acc[7] += xv * wb.w;
        }
        __syncthreads();
    }

    int row = row0 + r;
    if (row < N) {
        float di = g_dinv[row];
        float4 o0 = make_float4(acc[0] * di, acc[1] * di, acc[2] * di, acc[3] * di);
        float4 o1 = make_float4(acc[4] * di, acc[5] * di, acc[6] * di, acc[7] * di);
        float4* hp = (float4*)&g_hs[(size_t)row * HID + c0];
        hp[0] = o0; hp[1] = o1;
    }
}

// -------------------------- SpMM gather + bias + dot(w2) + sigmoid
// one warp per node; lane handles columns {2*lane, 2*lane+1}
__global__ void k_spmm(const float* __restrict__ b, const float* __restrict__ w2,
                       const float* __restrict__ b2, float* __restrict__ out, int N) {
    int gwarp = (blockIdx.x * blockDim.x + threadIdx.x) >> 5;
    int lane  = threadIdx.x & 31;
    if (gwarp >= N) return;
    int n = gwarp;

    int s = g_off[n];
    int e = g_off[n + 1];
    const float2* hs2 = (const float2*)g_hs;

    float ax = 0.f, ay = 0.f;
    for (int i = s; i < e; i++) {
        int src = g_esrc[i];
        float2 v = hs2[(size_t)src * 32 + lane];
        ax += v.x; ay += v.y;
    }
    float2 self = hs2[(size_t)n * 32 + lane];
    float di = g_dinv[n];
    float vx = di * (ax + self.x);
    float vy = di * (ay + self.y);

    float wx = w2[2 * lane], wy = w2[2 * lane + 1];
    float p = vx * wx + vy * wy + b[2 * lane] * wx + b[2 * lane + 1] * wy;
#pragma unroll
    for (int o = 16; o; o >>= 1) p += __shfl_xor_sync(0xFFFFFFFFu, p, o);
    if (lane == 0) {
        float z = p + b2[0];
        out[n] = 1.f / (1.f + expf(-z));
    }
}

// ---------------------------------------------------------------- launch
extern "C" void kernel_launch(void* const* d_in, const int* in_sizes, int n_in,
                              void* d_out, int out_size) {
    const float* x  = (const float*)d_in[0];
    const int*   ei = (const int*)d_in[1];    // int32! (JAX x64 disabled downcasts int64)
    const float* W  = (const float*)d_in[2];
    const float* b  = (const float*)d_in[3];
    const float* w2 = (const float*)d_in[4];
    const float* b2 = (const float*)d_in[5];
    float* out = (float*)d_out;

    int N = out_size;            // 100000 nodes
    int E = in_sizes[1] / 2;     // 1600000 edges

    k_init<<<(N + 255) / 256, 256>>>(N);
    k_count<<<(E + 255) / 256, 256>>>(ei + E, E, N);
    k_dinv<<<(N + 255) / 256, 256>>>(N);
    k_scan<<<1, 1024>>>(N);
    k_scatter<<<(E + 255) / 256, 256>>>(ei, E, N);
    k_gemm<<<(N + 31) / 32, 256>>>(x, W, N);
    k_spmm<<<(N + 7) / 8, 256>>>(b, w2, b2, out, N);
}

// round 7
// speedup vs baseline: 1.2005x; 1.2005x over previous
#include <cuda_runtime.h>
#include <math.h>

#define HID 64
#define MAXN 100000
#define MAXE 1600000

// Scratch (allocation-free rule: __device__ globals). 16B-aligned for vector access.
__device__ __align__(16) int   g_cnt[MAXN];
__device__ __align__(16) int   g_cur[MAXN];
__device__ __align__(16) int   g_off[MAXN + 1];
__device__ __align__(16) int   g_bsum[128];
__device__ __align__(16) int   g_esrc[MAXE];
__device__ __align__(16) float g_dinv[MAXN];
__device__ __align__(16) float g_hs[(size_t)MAXN * HID];

// ---------------------------------------------------------------- init
__global__ void k_init(int N) {
    int i = blockIdx.x * blockDim.x + threadIdx.x;
    if (i < N) { g_cnt[i] = 0; g_cur[i] = 0; }
}

// ------------------------------------------------------ degree histogram
__global__ void k_count(const int* __restrict__ dst, int E, int N) {
    int i = blockIdx.x * blockDim.x + threadIdx.x;
    if (i < E) {
        unsigned d = (unsigned)dst[i];
        if (d < (unsigned)N) atomicAdd(&g_cnt[d], 1);
    }
}

// ---------------- scan pass 1: per-block sums (1024 elems/block) + dinv
__global__ void k_scan1(int N) {
    int t = threadIdx.x;
    int i0 = blockIdx.x * 1024 + t * 4;
    int v0 = (i0 + 0 < N) ? g_cnt[i0 + 0] : 0;
    int v1 = (i0 + 1 < N) ? g_cnt[i0 + 1] : 0;
    int v2 = (i0 + 2 < N) ? g_cnt[i0 + 2] : 0;
    int v3 = (i0 + 3 < N) ? g_cnt[i0 + 3] : 0;
    if (i0 + 0 < N) g_dinv[i0 + 0] = rsqrtf((float)(v0 + 1));  // +1 self loop
    if (i0 + 1 < N) g_dinv[i0 + 1] = rsqrtf((float)(v1 + 1));
    if (i0 + 2 < N) g_dinv[i0 + 2] = rsqrtf((float)(v2 + 1));
    if (i0 + 3 < N) g_dinv[i0 + 3] = rsqrtf((float)(v3 + 1));
    int s = v0 + v1 + v2 + v3;
#pragma unroll
    for (int o = 16; o; o >>= 1) s += __shfl_xor_sync(0xFFFFFFFFu, s, o);
    __shared__ int wsum[8];
    if ((t & 31) == 0) wsum[t >> 5] = s;
    __syncthreads();
    if (t == 0) {
        int tot = 0;
#pragma unroll
        for (int w = 0; w < 8; w++) tot += wsum[w];
        g_bsum[blockIdx.x] = tot;
    }
}

// ---------------- scan pass 2: exclusive scan of <=128 block sums (1 block)
__global__ void k_scan2(int nb, int N) {
    __shared__ int sh[128];
    int t = threadIdx.x;
    int v = (t < nb) ? g_bsum[t] : 0;
    sh[t] = v;
    __syncthreads();
#pragma unroll
    for (int o = 1; o < 128; o <<= 1) {
        int a = 0;
        if (t >= o) a = sh[t - o];
        __syncthreads();
        sh[t] += a;
        __syncthreads();
    }
    if (t < nb) g_bsum[t] = sh[t] - v;     // exclusive
    if (t == 127) g_off[N] = sh[127];      // grand total (E in-bounds edges)
}

// ---------------- scan pass 3: local re-scan + block offset -> g_off
__global__ void k_scan3(int N) {
    __shared__ int sh[256];
    int t = threadIdx.x;
    int i0 = blockIdx.x * 1024 + t * 4;
    int v0 = (i0 + 0 < N) ? g_cnt[i0 + 0] : 0;
    int v1 = (i0 + 1 < N) ? g_cnt[i0 + 1] : 0;
    int v2 = (i0 + 2 < N) ? g_cnt[i0 + 2] : 0;
    int v3 = (i0 + 3 < N) ? g_cnt[i0 + 3] : 0;
    int s = v0 + v1 + v2 + v3;
    sh[t] = s;
    __syncthreads();
#pragma unroll
    for (int o = 1; o < 256; o <<= 1) {
        int a = 0;
        if (t >= o) a = sh[t - o];
        __syncthreads();
        sh[t] += a;
        __syncthreads();
    }
    int excl = sh[t] - s + g_bsum[blockIdx.x];
    if (i0 + 0 < N) g_off[i0 + 0] = excl;
    if (i0 + 1 < N) g_off[i0 + 1] = excl + v0;
    if (i0 + 2 < N) g_off[i0 + 2] = excl + v0 + v1;
    if (i0 + 3 < N) g_off[i0 + 3] = excl + v0 + v1 + v2;
}

// --------------------------------------------------- CSR edge scatter
__global__ void k_scatter(const int* __restrict__ ei, int E, int N) {
    int i = blockIdx.x * blockDim.x + threadIdx.x;
    if (i < E) {
        unsigned s = (unsigned)ei[i];
        unsigned d = (unsigned)ei[E + i];
        if (s < (unsigned)N && d < (unsigned)N) {
            int p = g_off[d] + atomicAdd(&g_cur[d], 1);
            g_esrc[p] = (int)s;
        }
    }
}

// ------------------------------------------ GEMM: hs = (x @ W) * dinv
// block = 256 threads, 32 rows/block, 8 cols/thread, K chunked by 64.
// static smem: W chunk [64x64] (16KB) + x chunk [32x65] (8.1KB) = 24.3KB
__global__ void k_gemm(const float* __restrict__ x, const float* __restrict__ W, int N) {
    __shared__ float Ws[64 * 64];
    __shared__ float xs[32 * 65];
    int tid = threadIdx.x;
    int row0 = blockIdx.x * 32;
    int c0 = (tid & 7) * 8;
    int r  = tid >> 3;

    const float4* W4 = (const float4*)W;
    const float4* x4 = (const float4*)x;
    float4* Ws4 = (float4*)Ws;

    float acc[8] = {0.f, 0.f, 0.f, 0.f, 0.f, 0.f, 0.f, 0.f};

    for (int kc = 0; kc < 4; kc++) {
#pragma unroll
        for (int i = tid; i < 1024; i += 256) Ws4[i] = W4[kc * 1024 + i];
#pragma unroll
        for (int i = tid; i < 512; i += 256) {
            int rr = i >> 4, cc = i & 15;
            float4 v = (row0 + rr < N) ? x4[(size_t)(row0 + rr) * 64 + kc * 16 + cc]
                                       : make_float4(0.f, 0.f, 0.f, 0.f);
            float* d = &xs[rr * 65 + cc * 4];
            d[0] = v.x; d[1] = v.y; d[2] = v.z; d[3] = v.w;
        }
        __syncthreads();

#pragma unroll 8
        for (int k = 0; k < 64; k++) {
            float xv = xs[r * 65 + k];
            float4 wa = *(const float4*)&Ws[k * 64 + c0];
            float4 wb = *(const float4*)&Ws[k * 64 + c0 + 4];
            acc[0] += xv * wa.x; acc[1] += xv * wa.y;
            acc[2] += xv * wa.z; acc[3] += xv * wa.w;
            acc[4] += xv * wb.x; acc[5] += xv * wb.y;
            acc[6] += xv * wb.z; acc[7] += xv * wb.w;
        }
        __syncthreads();
    }

    int row = row0 + r;
    if (row < N) {
        float di = g_dinv[row];
        float4 o0 = make_float4(acc[0] * di, acc[1] * di, acc[2] * di, acc[3] * di);
        float4 o1 = make_float4(acc[4] * di, acc[5] * di, acc[6] * di, acc[7] * di);
        float4* hp = (float4*)&g_hs[(size_t)row * HID + c0];
        hp[0] = o0; hp[1] = o1;
    }
}

// -------------------------- SpMM gather + bias + dot(w2) + sigmoid
// one warp per node; lane handles columns {2*lane, 2*lane+1}; edge loop x2 for MLP
__global__ void k_spmm(const float* __restrict__ b, const float* __restrict__ w2,
                       const float* __restrict__ b2, float* __restrict__ out, int N) {
    int gwarp = (blockIdx.x * blockDim.x + threadIdx.x) >> 5;
    int lane  = threadIdx.x & 31;
    if (gwarp >= N) return;
    int n = gwarp;

    int s = g_off[n];
    int e = g_off[n + 1];
    const float2* hs2 = (const float2*)g_hs;

    float ax = 0.f, ay = 0.f;
    float bx = 0.f, by = 0.f;
    int i = s;
    for (; i + 1 < e; i += 2) {
        int s0 = g_esrc[i];
        int s1 = g_esrc[i + 1];
        float2 v0 = hs2[(size_t)s0 * 32 + lane];
        float2 v1 = hs2[(size_t)s1 * 32 + lane];
        ax += v0.x; ay += v0.y;
        bx += v1.x; by += v1.y;
    }
    if (i < e) {
        int s0 = g_esrc[i];
        float2 v0 = hs2[(size_t)s0 * 32 + lane];
        ax += v0.x; ay += v0.y;
    }
    float2 self = hs2[(size_t)n * 32 + lane];
    float di = g_dinv[n];
    float vx = di * (ax + bx + self.x);
    float vy = di * (ay + by + self.y);

    float wx = w2[2 * lane], wy = w2[2 * lane + 1];
    float p = vx * wx + vy * wy + b[2 * lane] * wx + b[2 * lane + 1] * wy;
#pragma unroll
    for (int o = 16; o; o >>= 1) p += __shfl_xor_sync(0xFFFFFFFFu, p, o);
    if (lane == 0) {
        float z = p + b2[0];
        out[n] = 1.f / (1.f + expf(-z));
    }
}

// ---------------------------------------------------------------- launch
extern "C" void kernel_launch(void* const* d_in, const int* in_sizes, int n_in,
                              void* d_out, int out_size) {
    const float* x  = (const float*)d_in[0];
    const int*   ei = (const int*)d_in[1];    // int32 (JAX x64 disabled)
    const float* W  = (const float*)d_in[2];
    const float* b  = (const float*)d_in[3];
    const float* w2 = (const float*)d_in[4];
    const float* b2 = (const float*)d_in[5];
    float* out = (float*)d_out;

    int N = out_size;            // 100000 nodes
    int E = in_sizes[1] / 2;     // 1600000 edges
    int nb = (N + 1023) / 1024;  // scan blocks (<=128)

    k_init<<<(N + 255) / 256, 256>>>(N);
    k_count<<<(E + 255) / 256, 256>>>(ei + E, E, N);
    k_scan1<<<nb, 256>>>(N);
    k_scan2<<<1, 128>>>(nb, N);
    k_scan3<<<nb, 256>>>(N);
    k_scatter<<<(E + 255) / 256, 256>>>(ei, E, N);
    k_gemm<<<(N + 31) / 32, 256>>>(x, W, N);
    k_spmm<<<(N + 7) / 8, 256>>>(b, w2, b2, out, N);
}